// round 3
// baseline (speedup 1.0000x reference)
#include <cuda_runtime.h>
#include <cuda_fp16.h>
#include <stdint.h>

#define H      2048
#define FOURH  8192
#define TSEQ   2048
#define FUT    128
#define TOT    (TSEQ + FUT)
#define NB     148
#define NT     1024

#define NCH      12            // chunks per step (4 layer1 + 8 layer2)
#define CHUNK_H  28672         // halfs per chunk: 14 j * 4 g * 512 k
#define CHUNK_B  57344         // bytes per chunk
#define RING     3
#define SMEM_DYN (RING*CHUNK_B + 4096*4 + 112*4 + 64)

// ---------------- persistent device state ----------------
__device__ __align__(16) __half g_pack[(size_t)NB * NCH * CHUNK_H]; // ~102 MB packed weights
__device__ float  g_b1[FOURH];
__device__ float  g_b2[FOURH];
__device__ __align__(16) float g_h1[2][H];
__device__ __align__(16) float g_h2[2][H];
__device__ float  g_part[NB];
__device__ unsigned g_flags[NB];

// ---------------- prep: pack weights into per-block chunk layout ----------------
// grid = NB*NCH blocks; block (b, cid) fills one 28672-half chunk.
// chunk layout: [i(14)][g(4)][kk(512)] halfs.
//   cid 0..3 : w_hh1, k = cid*512 + kk
//   cid 4..11: d=cid-4; matrix = d&1 ? w_hh2 : w_ih2; k = (d>>1)*512 + kk
__global__ void prep_pack(const float* __restrict__ w_hh1,
                          const float* __restrict__ w_ih2,
                          const float* __restrict__ w_hh2)
{
    const int blk = blockIdx.x;
    const int b   = blk / NCH;
    const int cid = blk % NCH;
    __half* dst = g_pack + (size_t)blk * CHUNK_H;
    for (int e = threadIdx.x; e < CHUNK_H; e += blockDim.x) {
        const int i  = e >> 11;
        const int g  = (e >> 9) & 3;
        const int kk = e & 511;
        const int j  = b + i * NB;
        float v = 0.0f;
        if (j < H) {
            if (cid < 4) {
                v = w_hh1[((size_t)(g * H + j)) * H + cid * 512 + kk];
            } else {
                const int d = cid - 4;
                const float* W = (d & 1) ? w_hh2 : w_ih2;
                v = W[((size_t)(g * H + j)) * H + (d >> 1) * 512 + kk];
            }
        }
        dst[e] = __float2half_rn(v);
    }
}

__global__ void prep_misc(const float* __restrict__ b_ih1,
                          const float* __restrict__ b_hh1,
                          const float* __restrict__ b_ih2,
                          const float* __restrict__ b_hh2)
{
    const int i = blockIdx.x * blockDim.x + threadIdx.x;
    if (i < FOURH) {
        g_b1[i] = b_ih1[i] + b_hh1[i];
        g_b2[i] = b_ih2[i] + b_hh2[i];
    }
    if (i < NB) g_flags[i] = 0u;
}

// ---------------- flag-array grid barrier ----------------
__device__ __forceinline__ void grid_sync(int b, int tid, unsigned& target)
{
    ++target;
    __syncthreads();
    if (tid == 0)
        asm volatile("st.release.gpu.u32 [%0], %1;" :: "l"(g_flags + b), "r"(target) : "memory");
    if (tid < NB) {
        unsigned v;
        do {
            asm volatile("ld.acquire.gpu.u32 %0, [%1];" : "=r"(v) : "l"(g_flags + tid) : "memory");
        } while (v < target);
    }
    __syncthreads();
}

__device__ __forceinline__ float sigf(float x) { return 1.0f / (1.0f + __expf(-x)); }

__device__ __forceinline__ void fma8(const uint4& wv, const float4& ha, const float4& hb, float& a)
{
    const float2 f0 = __half22float2(*reinterpret_cast<const __half2*>(&wv.x));
    const float2 f1 = __half22float2(*reinterpret_cast<const __half2*>(&wv.y));
    const float2 f2 = __half22float2(*reinterpret_cast<const __half2*>(&wv.z));
    const float2 f3 = __half22float2(*reinterpret_cast<const __half2*>(&wv.w));
    a = fmaf(f0.x, ha.x, a); a = fmaf(f0.y, ha.y, a);
    a = fmaf(f1.x, ha.z, a); a = fmaf(f1.y, ha.w, a);
    a = fmaf(f2.x, hb.x, a); a = fmaf(f2.y, hb.y, a);
    a = fmaf(f3.x, hb.z, a); a = fmaf(f3.y, hb.w, a);
}

__device__ __forceinline__ void reduce4(float acc[4])
{
    #pragma unroll
    for (int g = 0; g < 4; ++g) {
        #pragma unroll
        for (int o = 16; o > 0; o >>= 1)
            acc[g] += __shfl_xor_sync(0xffffffffu, acc[g], o);
    }
}

// ---------------- main persistent kernel ----------------
__global__ void __launch_bounds__(NT, 1)
lstm_main(const float* __restrict__ input,
          const float* __restrict__ w_ih1,
          const float* __restrict__ w_lin,
          const float* __restrict__ b_lin,
          float* __restrict__ out)
{
    extern __shared__ char smem[];
    char*  sbuf = smem;                                    // RING * CHUNK_B
    float* s_hf = (float*)(smem + RING * CHUNK_B);         // 4096 floats
    float* s_g  = s_hf + 4096;                             // [14][4][2]
    float* s_o  = s_g + 112;                               // 14
    float* s_bc = s_o + 14;                                // 1

    const int b    = blockIdx.x;
    const int tid  = threadIdx.x;
    const int warp = tid >> 5;
    const int lane = tid & 31;
    const int nI   = (b < 124) ? 14 : 13;

    uint32_t sbase;
    asm("{.reg .u64 t0; cvta.to.shared.u64 t0, %1; cvt.u32.u64 %0, t0;}" : "=r"(sbase) : "l"(sbuf));

    const char* wsrc = (const char*)(g_pack + (size_t)b * NCH * CHUNK_H);

    // fixed warp task: (i, k-half)
    const bool act = (warp < 28);
    const int  iw  = warp >> 1;
    const int  kh  = warp & 1;
    const int  jw  = b + iw * NB;
    const int  klane = kh * 256 + lane * 8;   // element offset within a 512-k chunk

    // issue chunk cs (0..13, step-relative) into ring
    auto issue = [&](int cs, int t) {
        const bool valid = (t < TOT - 1) || (cs < NCH);
        if (valid) {
            const int wc   = (cs < NCH) ? cs : cs - NCH;
            const int slot = cs % RING;                 // t*NCH % RING == 0
            const uint32_t dst = sbase + slot * CHUNK_B;
            const char* src = wsrc + (size_t)wc * CHUNK_B;
            #pragma unroll
            for (int u = 0; u < 4; ++u) {
                const int idx = tid + u * NT;
                if (idx < CHUNK_B / 16)
                    asm volatile("cp.async.cg.shared.global [%0], [%1], 16;"
                                 :: "r"(dst + idx * 16), "l"(src + idx * 16));
            }
        }
        asm volatile("cp.async.commit_group;" ::: "memory");
    };

    // init state
    float c1v = 0.0f, c2v = 0.0f;
    if (tid < nI) {
        const int j = b + tid * NB;
        g_h1[0][j] = 0.0f; g_h1[1][j] = 0.0f;
        g_h2[0][j] = 0.0f; g_h2[1][j] = 0.0f;
    }
    unsigned target = 0;
    grid_sync(b, tid, target);

    const float blin = __ldg(b_lin);

    // prime the pipeline: chunks 0 and 1 of step 0
    issue(0, 0);
    issue(1, 0);

    for (int t = 0; t < TOT; ++t) {
        const int cur  = t & 1;
        const int prev = cur ^ 1;

        // ---- stage h1(prev) as float ----
        if (tid < 512)
            ((float4*)s_hf)[tid] = __ldcg(((const float4*)&g_h1[prev][0]) + tid);

        // ---- layer-1: 4 chunks ----
        float acc[4] = {0.f, 0.f, 0.f, 0.f};
        #pragma unroll
        for (int c = 0; c < 4; ++c) {
            asm volatile("cp.async.wait_group 1;" ::: "memory");
            __syncthreads();                 // chunk c visible; slot (c+2)%RING free
            issue(c + 2, t);
            if (act) {
                const __half* wb = (const __half*)(sbuf + (c % RING) * CHUNK_B);
                const float*  hp = s_hf + c * 512 + klane;
                const float4  ha = *(const float4*)hp;
                const float4  hb = *(const float4*)(hp + 4);
                #pragma unroll
                for (int g = 0; g < 4; ++g) {
                    const uint4 wv = *(const uint4*)(wb + (iw * 4 + g) * 512 + klane);
                    fma8(wv, ha, hb, acc[g]);
                }
            }
        }
        reduce4(acc);
        if (act && lane == 0) {
            #pragma unroll
            for (int g = 0; g < 4; ++g) s_g[(iw * 4 + g) * 2 + kh] = acc[g];
        }
        __syncthreads();

        // ---- layer-1 elementwise ----
        if (tid < nI) {
            const float x = (t < TSEQ) ? __ldg(input + t) : *s_bc;
            const int j = b + tid * NB;
            const float gi = s_g[(tid*4+0)*2] + s_g[(tid*4+0)*2+1] + g_b1[j]        + __ldg(w_ih1 + j)        * x;
            const float gf = s_g[(tid*4+1)*2] + s_g[(tid*4+1)*2+1] + g_b1[j + 2048] + __ldg(w_ih1 + j + 2048) * x;
            const float gg = s_g[(tid*4+2)*2] + s_g[(tid*4+2)*2+1] + g_b1[j + 4096] + __ldg(w_ih1 + j + 4096) * x;
            const float go = s_g[(tid*4+3)*2] + s_g[(tid*4+3)*2+1] + g_b1[j + 6144] + __ldg(w_ih1 + j + 6144) * x;
            c1v = sigf(gf) * c1v + sigf(gi) * tanhf(gg);
            g_h1[cur][j] = sigf(go) * tanhf(c1v);
        }
        grid_sync(b, tid, target);

        // ---- stage h1(cur) | h2(prev) ----
        if (tid < 512)
            ((float4*)s_hf)[tid] = __ldcg(((const float4*)&g_h1[cur][0]) + tid);
        else
            ((float4*)s_hf)[tid] = __ldcg(((const float4*)&g_h2[prev][0]) + (tid - 512));

        // ---- layer-2: 8 chunks (w_ih2/w_hh2 interleaved per 512-k segment) ----
        acc[0] = acc[1] = acc[2] = acc[3] = 0.f;
        #pragma unroll
        for (int c = 4; c < 12; ++c) {
            asm volatile("cp.async.wait_group 1;" ::: "memory");
            __syncthreads();
            issue(c + 2, t);
            if (act) {
                const int d   = c - 4;
                const int mtx = d & 1;       // 0: w_ih2 (vs h1cur), 1: w_hh2 (vs h2prev)
                const int ks  = d >> 1;
                const __half* wb = (const __half*)(sbuf + (c % RING) * CHUNK_B);
                const float*  hp = s_hf + mtx * 2048 + ks * 512 + klane;
                const float4  ha = *(const float4*)hp;
                const float4  hb = *(const float4*)(hp + 4);
                #pragma unroll
                for (int g = 0; g < 4; ++g) {
                    const uint4 wv = *(const uint4*)(wb + (iw * 4 + g) * 512 + klane);
                    fma8(wv, ha, hb, acc[g]);
                }
            }
        }
        reduce4(acc);
        if (act && lane == 0) {
            #pragma unroll
            for (int g = 0; g < 4; ++g) s_g[(iw * 4 + g) * 2 + kh] = acc[g];
        }
        __syncthreads();

        // ---- layer-2 elementwise ----
        if (tid < nI) {
            const int j = b + tid * NB;
            const float gi = s_g[(tid*4+0)*2] + s_g[(tid*4+0)*2+1] + g_b2[j];
            const float gf = s_g[(tid*4+1)*2] + s_g[(tid*4+1)*2+1] + g_b2[j + 2048];
            const float gg = s_g[(tid*4+2)*2] + s_g[(tid*4+2)*2+1] + g_b2[j + 4096];
            const float go = s_g[(tid*4+3)*2] + s_g[(tid*4+3)*2+1] + g_b2[j + 6144];
            c2v = sigf(gf) * c2v + sigf(gi) * tanhf(gg);
            const float h = sigf(go) * tanhf(c2v);
            g_h2[cur][j] = h;
            s_o[tid] = h * __ldg(w_lin + j);
        }
        __syncthreads();
        if (tid == 0) {
            float s = 0.0f;
            #pragma unroll
            for (int i = 0; i < 14; ++i) if (i < nI) s += s_o[i];
            g_part[b] = s;
        }
        grid_sync(b, tid, target);

        // ---- scalar output reduce (warp 0; overlaps next step's staging) ----
        if (warp == 0) {
            float s = 0.0f;
            #pragma unroll
            for (int p = lane; p < NB; p += 32) s += __ldcg(&g_part[p]);
            #pragma unroll
            for (int o = 16; o > 0; o >>= 1) s += __shfl_xor_sync(0xffffffffu, s, o);
            if (lane == 0) {
                const float y = s + blin;
                *s_bc = y;                   // published by the c=0 __syncthreads next step
                if (b == 0) out[t] = y;
            }
        }
    }
}

// ---------------- launch ----------------
extern "C" void kernel_launch(void* const* d_in, const int* in_sizes, int n_in,
                              void* d_out, int out_size)
{
    const float* input = (const float*)d_in[0];
    const float* w_ih1 = (const float*)d_in[1];
    const float* w_hh1 = (const float*)d_in[2];
    const float* b_ih1 = (const float*)d_in[3];
    const float* b_hh1 = (const float*)d_in[4];
    const float* w_ih2 = (const float*)d_in[5];
    const float* w_hh2 = (const float*)d_in[6];
    const float* b_ih2 = (const float*)d_in[7];
    const float* b_hh2 = (const float*)d_in[8];
    const float* w_lin = (const float*)d_in[9];
    const float* b_lin = (const float*)d_in[10];
    float* out = (float*)d_out;

    cudaFuncSetAttribute(lstm_main, cudaFuncAttributeMaxDynamicSharedMemorySize, SMEM_DYN);

    prep_pack<<<NB * NCH, 256>>>(w_hh1, w_ih2, w_hh2);
    prep_misc<<<(FOURH + 255) / 256, 256>>>(b_ih1, b_hh1, b_ih2, b_hh2);
    lstm_main<<<NB, NT, SMEM_DYN>>>(input, w_ih1, w_lin, b_lin, out);
}

// round 5
// speedup vs baseline: 1.0318x; 1.0318x over previous
#include <cuda_runtime.h>
#include <cuda_fp16.h>
#include <stdint.h>

#define H      2048
#define FOURH  8192
#define TSEQ   2048
#define FUT    128
#define TOT    (TSEQ + FUT)
#define NB     148
#define NT     896            // 28 warps = 14 j-slots x 2 k-halves

#define NCH      12           // chunks per step: 4 layer1 + 8 layer2
#define CHUNK_H  28672        // halfs per chunk: 14 j * 4 g * 512 k

// ---------------- persistent device state ----------------
__device__ __align__(16) __half g_pack[(size_t)NB * NCH * CHUNK_H];  // ~102 MB packed fp16 weights
__device__ float  g_b1[FOURH];
__device__ float  g_b2[FOURH];
__device__ __align__(16) float g_h1[2][H];
__device__ __align__(16) float g_h2[2][H];
__device__ float  g_part[NB];
__device__ unsigned g_flags[NB];

// ---------------- prep: pack weights into per-block chunk layout ----------------
// chunk layout: [i(14)][g(4)][kk(512)] halfs.
//   cid 0..3 : w_hh1, k = cid*512 + kk
//   cid 4..11: d=cid-4; matrix = d&1 ? w_hh2 : w_ih2; k = (d>>1)*512 + kk
__global__ void prep_pack(const float* __restrict__ w_hh1,
                          const float* __restrict__ w_ih2,
                          const float* __restrict__ w_hh2)
{
    const int blk = blockIdx.x;
    const int b   = blk / NCH;
    const int cid = blk % NCH;
    __half* dst = g_pack + (size_t)blk * CHUNK_H;
    for (int e = threadIdx.x; e < CHUNK_H; e += blockDim.x) {
        const int i  = e >> 11;
        const int g  = (e >> 9) & 3;
        const int kk = e & 511;
        const int j  = b + i * NB;
        float v = 0.0f;
        if (j < H) {
            if (cid < 4) {
                v = w_hh1[((size_t)(g * H + j)) * H + cid * 512 + kk];
            } else {
                const int d = cid - 4;
                const float* W = (d & 1) ? w_hh2 : w_ih2;
                v = W[((size_t)(g * H + j)) * H + (d >> 1) * 512 + kk];
            }
        }
        dst[e] = __float2half_rn(v);
    }
}

__global__ void prep_misc(const float* __restrict__ b_ih1,
                          const float* __restrict__ b_hh1,
                          const float* __restrict__ b_ih2,
                          const float* __restrict__ b_hh2)
{
    const int i = blockIdx.x * blockDim.x + threadIdx.x;
    if (i < FOURH) {
        g_b1[i] = b_ih1[i] + b_hh1[i];
        g_b2[i] = b_ih2[i] + b_hh2[i];
    }
    if (i < NB)  g_flags[i] = 0u;
    if (i < H) { g_h1[0][i] = 0.f; g_h1[1][i] = 0.f; g_h2[0][i] = 0.f; g_h2[1][i] = 0.f; }
}

// ---------------- flag-array grid barrier ----------------
__device__ __forceinline__ void grid_sync(int b, int tid, unsigned& target)
{
    ++target;
    __syncthreads();
    if (tid == 0)
        asm volatile("st.release.gpu.u32 [%0], %1;" :: "l"(g_flags + b), "r"(target) : "memory");
    if (tid < NB) {
        unsigned v;
        do {
            asm volatile("ld.acquire.gpu.u32 %0, [%1];" : "=r"(v) : "l"(g_flags + tid) : "memory");
        } while (v < target);
    }
    __syncthreads();
}

__device__ __forceinline__ float sigf(float x) { return 1.0f / (1.0f + __expf(-x)); }

__device__ __forceinline__ void fma8(const uint4& wv, const float4& ha, const float4& hb, float& a)
{
    const float2 f0 = __half22float2(*reinterpret_cast<const __half2*>(&wv.x));
    const float2 f1 = __half22float2(*reinterpret_cast<const __half2*>(&wv.y));
    const float2 f2 = __half22float2(*reinterpret_cast<const __half2*>(&wv.z));
    const float2 f3 = __half22float2(*reinterpret_cast<const __half2*>(&wv.w));
    a = fmaf(f0.x, ha.x, a); a = fmaf(f0.y, ha.y, a);
    a = fmaf(f1.x, ha.z, a); a = fmaf(f1.y, ha.w, a);
    a = fmaf(f2.x, hb.x, a); a = fmaf(f2.y, hb.y, a);
    a = fmaf(f3.x, hb.z, a); a = fmaf(f3.y, hb.w, a);
}

__device__ __forceinline__ void reduce4(float acc[4])
{
    #pragma unroll
    for (int g = 0; g < 4; ++g) {
        #pragma unroll
        for (int o = 16; o > 0; o >>= 1)
            acc[g] += __shfl_xor_sync(0xffffffffu, acc[g], o);
    }
}

// ---------------- main persistent kernel ----------------
__global__ void __launch_bounds__(NT, 1)
lstm_main(const float* __restrict__ input,
          const float* __restrict__ w_ih1,
          const float* __restrict__ w_lin,
          const float* __restrict__ b_lin,
          float* __restrict__ out)
{
    __shared__ __align__(16) float s_hf[2 * H];   // [0:2048) h-layer1, [2048:4096) h2prev
    __shared__ float s_g[14 * 4 * 2];             // [i][g][kh]

    const int b    = blockIdx.x;
    const int tid  = threadIdx.x;
    const int warp = tid >> 5;
    const int lane = tid & 31;
    const int nI   = (b < 124) ? 14 : 13;

    // fixed warp task: (iw, kh)
    const int iw    = warp >> 1;
    const int kh    = warp & 1;
    const int klane = kh * 256 + lane * 8;

    // per-warp base inside a chunk
    const __half* wbase = g_pack + (size_t)b * NCH * CHUNK_H + iw * 2048 + klane;
    #define WCHUNK(c) (wbase + (size_t)(c) * CHUNK_H)

    uint4 buf[2][4];
    #define LD4(dst, c) { const __half* _p = WCHUNK(c); \
        _Pragma("unroll") for (int g = 0; g < 4; ++g) \
            dst[g] = __ldg((const uint4*)(_p + g * 512)); }

    // init: zero s_hf, state
    for (int q = tid; q < 2 * H; q += NT) s_hf[q] = 0.0f;
    float c1v = 0.0f, c2v = 0.0f;
    unsigned target = 0;
    grid_sync(b, tid, target);     // also orders prep_misc zeros (redundant but cheap)

    const float blin = __ldg(b_lin);
    float xnext = 0.0f;            // warp-0 carried recurrent output

    // prime chunk 0
    LD4(buf[0], 0);

    for (int t = 0; t < TOT; ++t) {
        const int cur = t & 1;

        // ================= layer 1: chunks 0..3 over s_hf[0:2048) =================
        float acc[4] = {0.f, 0.f, 0.f, 0.f};
        #pragma unroll
        for (int c = 0; c < 4; ++c) {
            const int nc = (c < 3) ? c + 1 : 4;
            LD4(buf[(c + 1) & 1], nc);
            const float4 ha = *(const float4*)(s_hf + c * 512 + klane);
            const float4 hb = *(const float4*)(s_hf + c * 512 + klane + 4);
            #pragma unroll
            for (int g = 0; g < 4; ++g) fma8(buf[c & 1][g], ha, hb, acc[g]);
        }
        reduce4(acc);
        if (lane == 0) {
            #pragma unroll
            for (int g = 0; g < 4; ++g) s_g[(iw * 4 + g) * 2 + kh] = acc[g];
        }
        __syncthreads();

        // ---- layer-1 elementwise (warp 0 only; x carried in registers) ----
        if (warp == 0 && lane < nI) {
            const float x = (t < TSEQ) ? __ldg(input + t) : xnext;
            const int j = b + lane * NB;
            const float gi = s_g[(lane*4+0)*2] + s_g[(lane*4+0)*2+1] + g_b1[j]        + __ldg(w_ih1 + j)        * x;
            const float gf = s_g[(lane*4+1)*2] + s_g[(lane*4+1)*2+1] + g_b1[j + 2048] + __ldg(w_ih1 + j + 2048) * x;
            const float gg = s_g[(lane*4+2)*2] + s_g[(lane*4+2)*2+1] + g_b1[j + 4096] + __ldg(w_ih1 + j + 4096) * x;
            const float go = s_g[(lane*4+3)*2] + s_g[(lane*4+3)*2+1] + g_b1[j + 6144] + __ldg(w_ih1 + j + 6144) * x;
            c1v = sigf(gf) * c1v + sigf(gi) * tanhf(gg);
            g_h1[cur][j] = sigf(go) * tanhf(c1v);
        }
        grid_sync(b, tid, target);

        // ---- stage h1(cur) | h2(prev) : 1024 float4 ----
        #pragma unroll
        for (int q = tid; q < 1024; q += NT) {
            if (q < 512)
                ((float4*)s_hf)[q] = __ldcg(((const float4*)&g_h1[cur][0]) + q);
            else
                ((float4*)s_hf)[q] = __ldcg(((const float4*)&g_h2[cur ^ 1][0]) + (q - 512));
        }
        __syncthreads();

        // ================= layer 2: chunks 4..11 =================
        acc[0] = acc[1] = acc[2] = acc[3] = 0.f;
        #pragma unroll
        for (int c = 4; c < 12; ++c) {
            const int nc = (c < 11) ? c + 1 : 0;     // c==11 prefetches next step's chunk 0
            LD4(buf[(c + 1) & 1], nc);
            const int d   = c - 4;
            const int hoff = (d & 1) * 2048 + (d >> 1) * 512 + klane;
            const float4 ha = *(const float4*)(s_hf + hoff);
            const float4 hb = *(const float4*)(s_hf + hoff + 4);
            #pragma unroll
            for (int g = 0; g < 4; ++g) fma8(buf[c & 1][g], ha, hb, acc[g]);
        }
        reduce4(acc);
        if (lane == 0) {
            #pragma unroll
            for (int g = 0; g < 4; ++g) s_g[(iw * 4 + g) * 2 + kh] = acc[g];
        }
        __syncthreads();

        // ---- layer-2 elementwise + partial output (warp 0 only) ----
        if (warp == 0) {
            float contrib = 0.0f;
            if (lane < nI) {
                const int j = b + lane * NB;
                const float gi = s_g[(lane*4+0)*2] + s_g[(lane*4+0)*2+1] + g_b2[j];
                const float gf = s_g[(lane*4+1)*2] + s_g[(lane*4+1)*2+1] + g_b2[j + 2048];
                const float gg = s_g[(lane*4+2)*2] + s_g[(lane*4+2)*2+1] + g_b2[j + 4096];
                const float go = s_g[(lane*4+3)*2] + s_g[(lane*4+3)*2+1] + g_b2[j + 6144];
                c2v = sigf(gf) * c2v + sigf(gi) * tanhf(gg);
                const float h = sigf(go) * tanhf(c2v);
                g_h2[cur][j] = h;
                contrib = h * __ldg(w_lin + j);
            }
            #pragma unroll
            for (int o = 16; o > 0; o >>= 1) contrib += __shfl_xor_sync(0xffffffffu, contrib, o);
            if (lane == 0) g_part[b] = contrib;
        }
        grid_sync(b, tid, target);

        // ---- scalar output reduce (warp 0; overlaps other warps' next-step dots) ----
        if (warp == 0) {
            float s = 0.0f;
            #pragma unroll
            for (int p = lane; p < NB; p += 32) s += __ldcg(&g_part[p]);
            #pragma unroll
            for (int o = 16; o > 0; o >>= 1) s += __shfl_xor_sync(0xffffffffu, s, o);
            xnext = s + blin;
            if (b == 0 && lane == 0) out[t] = xnext;
        }
    }
    #undef LD4
    #undef WCHUNK
}

// ---------------- launch ----------------
extern "C" void kernel_launch(void* const* d_in, const int* in_sizes, int n_in,
                              void* d_out, int out_size)
{
    const float* input = (const float*)d_in[0];
    const float* w_ih1 = (const float*)d_in[1];
    const float* w_hh1 = (const float*)d_in[2];
    const float* b_ih1 = (const float*)d_in[3];
    const float* b_hh1 = (const float*)d_in[4];
    const float* w_ih2 = (const float*)d_in[5];
    const float* w_hh2 = (const float*)d_in[6];
    const float* b_ih2 = (const float*)d_in[7];
    const float* b_hh2 = (const float*)d_in[8];
    const float* w_lin = (const float*)d_in[9];
    const float* b_lin = (const float*)d_in[10];
    float* out = (float*)d_out;

    prep_pack<<<NB * NCH, 256>>>(w_hh1, w_ih2, w_hh2);
    prep_misc<<<(FOURH + 255) / 256, 256>>>(b_ih1, b_hh1, b_ih2, b_hh2);
    lstm_main<<<NB, NT>>>(input, w_ih1, w_lin, b_lin, out);
}

// round 6
// speedup vs baseline: 2.0541x; 1.9908x over previous
#include <cuda_runtime.h>
#include <cuda_fp16.h>
#include <stdint.h>

#define H      2048
#define FOURH  8192
#define TSEQ   2048
#define FUT    128
#define TOT    (TSEQ + FUT)
#define NB     148
#define NT     1024

#define GATE_STRIDE ((size_t)2048 * (size_t)H)

// ---------------- persistent device state ----------------
__device__ __align__(16) __half g_w1 [(size_t)FOURH * H];   // w_hh1 fp16
__device__ __align__(16) __half g_w2i[(size_t)FOURH * H];   // w_ih2 fp16
__device__ __align__(16) __half g_w2h[(size_t)FOURH * H];   // w_hh2 fp16
__device__ float  g_b1[FOURH];
__device__ float  g_b2[FOURH];
__device__ __align__(16) float g_h1[2][H];
__device__ __align__(16) float g_h2[2][H];
__device__ float  g_part[2][NB];            // parity double-buffered output partials
__device__ unsigned g_count;
__device__ unsigned g_sense;

// ---------------- prep ----------------
__global__ void prep_kernel(const float* __restrict__ w_hh1,
                            const float* __restrict__ w_ih2,
                            const float* __restrict__ w_hh2,
                            const float* __restrict__ b_ih1,
                            const float* __restrict__ b_hh1,
                            const float* __restrict__ b_ih2,
                            const float* __restrict__ b_hh2)
{
    const size_t n = (size_t)FOURH * H;
    const size_t stride = (size_t)gridDim.x * blockDim.x;
    size_t i0 = (size_t)blockIdx.x * blockDim.x + threadIdx.x;
    for (size_t k = i0; k < n; k += stride) {
        g_w1 [k] = __float2half_rn(w_hh1[k]);
        g_w2i[k] = __float2half_rn(w_ih2[k]);
        g_w2h[k] = __float2half_rn(w_hh2[k]);
    }
    if (i0 < FOURH) {
        g_b1[i0] = b_ih1[i0] + b_hh1[i0];
        g_b2[i0] = b_ih2[i0] + b_hh2[i0];
    }
    if (i0 < H) {
        g_h1[0][i0] = 0.f; g_h1[1][i0] = 0.f;
        g_h2[0][i0] = 0.f; g_h2[1][i0] = 0.f;
    }
    if (i0 < NB) { g_part[0][i0] = 0.f; g_part[1][i0] = 0.f; }
    if (i0 == 0) { g_count = 0u; g_sense = 0u; }
}

// ---------------- grid barrier: single atomic counter + monotonic sense (R1, proven) ----
__device__ __forceinline__ void grid_sync(unsigned* phase)
{
    __syncthreads();
    if (threadIdx.x == 0) {
        const unsigned target = ++(*phase);
        __threadfence();
        if (atomicAdd(&g_count, 1u) == (unsigned)(NB - 1)) {
            g_count = 0u;
            __threadfence();
            atomicExch(&g_sense, target);
        } else {
            while (*((volatile unsigned*)&g_sense) < target) { }
            __threadfence();
        }
    }
    __syncthreads();
}

__device__ __forceinline__ float sigf(float x) { return 1.0f / (1.0f + __expf(-x)); }

__device__ __forceinline__ void fma8(const uint4& wv, const float4& ha, const float4& hb, float& a)
{
    const float2 f0 = __half22float2(*reinterpret_cast<const __half2*>(&wv.x));
    const float2 f1 = __half22float2(*reinterpret_cast<const __half2*>(&wv.y));
    const float2 f2 = __half22float2(*reinterpret_cast<const __half2*>(&wv.z));
    const float2 f3 = __half22float2(*reinterpret_cast<const __half2*>(&wv.w));
    a = fmaf(f0.x, ha.x, a); a = fmaf(f0.y, ha.y, a);
    a = fmaf(f1.x, ha.z, a); a = fmaf(f1.y, ha.w, a);
    a = fmaf(f2.x, hb.x, a); a = fmaf(f2.y, hb.y, a);
    a = fmaf(f3.x, hb.z, a); a = fmaf(f3.y, hb.w, a);
}

// 4-gate dot over 1024 elems, register double-buffered; pre[] holds the m=0 loads
// (issued by the caller, possibly before a barrier).
__device__ __forceinline__ void dot4_pre(const __half* __restrict__ w, const float* hs,
                                         int lane, float acc[4], uint4 pre[4])
{
    acc[0] = acc[1] = acc[2] = acc[3] = 0.0f;
    uint4 buf[4];
    #pragma unroll
    for (int m = 0; m < 4; ++m) {
        if (m < 3) {
            #pragma unroll
            for (int g = 0; g < 4; ++g)
                buf[g] = __ldg((const uint4*)(w + (size_t)g * GATE_STRIDE + (m + 1) * 256 + lane * 8));
        }
        const int base = m * 256 + lane * 8;
        const float4 ha = *reinterpret_cast<const float4*>(hs + base);
        const float4 hb = *reinterpret_cast<const float4*>(hs + base + 4);
        #pragma unroll
        for (int g = 0; g < 4; ++g) fma8(pre[g], ha, hb, acc[g]);
        #pragma unroll
        for (int g = 0; g < 4; ++g) pre[g] = buf[g];
    }
}

__device__ __forceinline__ void reduce4(float acc[4])
{
    #pragma unroll
    for (int g = 0; g < 4; ++g) {
        #pragma unroll
        for (int o = 16; o > 0; o >>= 1)
            acc[g] += __shfl_xor_sync(0xffffffffu, acc[g], o);
    }
}

// ---------------- main persistent kernel ----------------
__global__ void __launch_bounds__(NT, 1)
lstm_main(const float* __restrict__ input,
          const float* __restrict__ w_ih1,
          const float* __restrict__ w_lin,
          const float* __restrict__ b_lin,
          float* __restrict__ out)
{
    __shared__ __align__(16) float s_h[2 * H];    // [0:H) h1, [H:2H) h2(prev)
    __shared__ float s_g1[14][4][2];
    __shared__ float s_g2[14][4][4];

    const int b    = blockIdx.x;
    const int tid  = threadIdx.x;
    const int warp = tid >> 5;
    const int lane = tid & 31;
    const int nI   = (b < 124) ? 14 : 13;

    unsigned phase = 0;

    // layer-1 task (fixed): warp < 28 active
    const bool  t1  = (warp < 28) && ((warp >> 1) < nI);
    const int   i1  = warp >> 1;
    const int   kh1 = warp & 1;
    const __half* w1p = g_w1 + (size_t)(b + i1 * NB) * H + kh1 * (H / 2);

    // layer-2 tasks (R1 mapping): tA = warp (<52 always), tB = warp+32
    const int iA = warp >> 2, subA = warp & 3, srcA = subA >> 1, khA = subA & 1;
    const __half* wAp = (srcA ? g_w2h : g_w2i) + (size_t)(b + iA * NB) * H + khA * (H / 2);
    const int tB = warp + 32;
    const bool tBv = (tB < nI * 4);
    const int iB = tB >> 2, subB = tB & 3, srcB = subB >> 1, khB = subB & 1;
    const __half* wBp = (srcB ? g_w2h : g_w2i) + (size_t)(b + iB * NB) * H + khB * (H / 2);

    // zero s_h (h states zeroed by prep, same-stream ordering)
    for (int q = tid; q < 2 * H; q += NT) s_h[q] = 0.0f;
    __syncthreads();

    const float blin = __ldg(b_lin);
    float c1v = 0.0f, c2v = 0.0f;     // warp-0 lane-resident cell states
    float xnext = 0.0f;               // warp-0 resident recurrent scalar

    // prime layer-1 m=0 for t=0
    uint4 pre1[4];
    if (t1) {
        #pragma unroll
        for (int g = 0; g < 4; ++g)
            pre1[g] = __ldg((const uint4*)(w1p + (size_t)g * GATE_STRIDE + lane * 8));
    }

    for (int t = 0; t < TOT; ++t) {
        const int cur  = t & 1;
        const int prev = cur ^ 1;

        // ================= layer 1 (reads s_h[0:H) = h1(t-1)) =================
        if (t1) {
            float acc[4];
            dot4_pre(w1p, s_h + kh1 * (H / 2), lane, acc, pre1);
            reduce4(acc);
            if (lane == 0) {
                s_g1[i1][0][kh1] = acc[0]; s_g1[i1][1][kh1] = acc[1];
                s_g1[i1][2][kh1] = acc[2]; s_g1[i1][3][kh1] = acc[3];
            }
        }
        __syncthreads();

        // ---- layer-1 elementwise (warp 0) ----
        if (warp == 0 && lane < nI) {
            const float x = (t < TSEQ) ? __ldg(input + t) : xnext;
            const int j = b + lane * NB;
            const float gi = s_g1[lane][0][0] + s_g1[lane][0][1] + g_b1[j]        + __ldg(w_ih1 + j)        * x;
            const float gf = s_g1[lane][1][0] + s_g1[lane][1][1] + g_b1[j + 2048] + __ldg(w_ih1 + j + 2048) * x;
            const float gg = s_g1[lane][2][0] + s_g1[lane][2][1] + g_b1[j + 4096] + __ldg(w_ih1 + j + 4096) * x;
            const float go = s_g1[lane][3][0] + s_g1[lane][3][1] + g_b1[j + 6144] + __ldg(w_ih1 + j + 6144) * x;
            c1v = sigf(gf) * c1v + sigf(gi) * tanhf(gg);
            g_h1[cur][j] = sigf(go) * tanhf(c1v);
        }

        // prefetch layer-2 task A m=0 (crosses barrier A)
        uint4 preA[4];
        #pragma unroll
        for (int g = 0; g < 4; ++g)
            preA[g] = __ldg((const uint4*)(wAp + (size_t)g * GATE_STRIDE + lane * 8));

        grid_sync(&phase);            // ===== barrier A =====

        // ---- lazy output for step t-1 (open-loop phase only; block 0) ----
        if (b == 0 && warp == 0 && t > 0 && (t - 1) < TSEQ - 1) {
            float s = 0.0f;
            #pragma unroll
            for (int p = lane; p < NB; p += 32) s += __ldcg(&g_part[prev][p]);
            #pragma unroll
            for (int o = 16; o > 0; o >>= 1) s += __shfl_xor_sync(0xffffffffu, s, o);
            if (lane == 0) out[t - 1] = s + blin;
        }

        // ---- stage h1(cur) | h2(prev) : 1024 float4 ----
        if (tid < 512)
            *reinterpret_cast<float4*>(s_h + 4 * tid) =
                __ldcg(reinterpret_cast<const float4*>(&g_h1[cur][4 * tid]));
        else
            *reinterpret_cast<float4*>(s_h + 4 * tid) =
                __ldcg(reinterpret_cast<const float4*>(&g_h2[prev][4 * (tid - 512)]));
        __syncthreads();

        // ================= layer 2: task A, then task B =================
        {
            float acc[4];
            dot4_pre(wAp, s_h + srcA * H + khA * (H / 2), lane, acc, preA);
            reduce4(acc);
            if (lane == 0) {
                s_g2[iA][0][subA] = acc[0]; s_g2[iA][1][subA] = acc[1];
                s_g2[iA][2][subA] = acc[2]; s_g2[iA][3][subA] = acc[3];
            }
        }
        if (tBv) {
            uint4 preB[4];
            #pragma unroll
            for (int g = 0; g < 4; ++g)
                preB[g] = __ldg((const uint4*)(wBp + (size_t)g * GATE_STRIDE + lane * 8));
            float acc[4];
            dot4_pre(wBp, s_h + srcB * H + khB * (H / 2), lane, acc, preB);
            reduce4(acc);
            if (lane == 0) {
                s_g2[iB][0][subB] = acc[0]; s_g2[iB][1][subB] = acc[1];
                s_g2[iB][2][subB] = acc[2]; s_g2[iB][3][subB] = acc[3];
            }
        }
        __syncthreads();

        // ---- layer-2 elementwise + block partial (warp 0, shuffle-reduced) ----
        if (warp == 0) {
            float contrib = 0.0f;
            if (lane < nI) {
                const int j = b + lane * NB;
                const float gi = s_g2[lane][0][0] + s_g2[lane][0][1] + s_g2[lane][0][2] + s_g2[lane][0][3] + g_b2[j];
                const float gf = s_g2[lane][1][0] + s_g2[lane][1][1] + s_g2[lane][1][2] + s_g2[lane][1][3] + g_b2[j + 2048];
                const float gg = s_g2[lane][2][0] + s_g2[lane][2][1] + s_g2[lane][2][2] + s_g2[lane][2][3] + g_b2[j + 4096];
                const float go = s_g2[lane][3][0] + s_g2[lane][3][1] + s_g2[lane][3][2] + s_g2[lane][3][3] + g_b2[j + 6144];
                c2v = sigf(gf) * c2v + sigf(gi) * tanhf(gg);
                const float h = sigf(go) * tanhf(c2v);
                g_h2[cur][j] = h;
                contrib = h * __ldg(w_lin + j);
            }
            #pragma unroll
            for (int o = 16; o > 0; o >>= 1) contrib += __shfl_xor_sync(0xffffffffu, contrib, o);
            if (lane == 0) g_part[cur][b] = contrib;
        }

        // prefetch next step's layer-1 m=0 (crosses barrier B / loop tail)
        if (t1) {
            #pragma unroll
            for (int g = 0; g < 4; ++g)
                pre1[g] = __ldg((const uint4*)(w1p + (size_t)g * GATE_STRIDE + lane * 8));
        }

        // ===== barrier B only when the scalar output feeds back (or final step) =====
        if (t >= TSEQ - 1) {
            grid_sync(&phase);
            if (warp == 0) {
                float s = 0.0f;
                #pragma unroll
                for (int p = lane; p < NB; p += 32) s += __ldcg(&g_part[cur][p]);
                #pragma unroll
                for (int o = 16; o > 0; o >>= 1) s += __shfl_xor_sync(0xffffffffu, s, o);
                xnext = s + blin;
                if (b == 0 && lane == 0) out[t] = xnext;
            }
        }
    }
}

// ---------------- launch ----------------
extern "C" void kernel_launch(void* const* d_in, const int* in_sizes, int n_in,
                              void* d_out, int out_size)
{
    const float* input = (const float*)d_in[0];
    const float* w_ih1 = (const float*)d_in[1];
    const float* w_hh1 = (const float*)d_in[2];
    const float* b_ih1 = (const float*)d_in[3];
    const float* b_hh1 = (const float*)d_in[4];
    const float* w_ih2 = (const float*)d_in[5];
    const float* w_hh2 = (const float*)d_in[6];
    const float* b_ih2 = (const float*)d_in[7];
    const float* b_hh2 = (const float*)d_in[8];
    const float* w_lin = (const float*)d_in[9];
    const float* b_lin = (const float*)d_in[10];
    float* out = (float*)d_out;

    prep_kernel<<<1024, 256>>>(w_hh1, w_ih2, w_hh2, b_ih1, b_hh1, b_ih2, b_hh2);
    lstm_main<<<NB, NT>>>(input, w_ih1, w_lin, b_lin, out);
}